// round 7
// baseline (speedup 1.0000x reference)
#include <cuda_runtime.h>
#include <math.h>

#define NN 17
#define DD 512
#define HH 8
#define MM 256
#define CIN 515

typedef unsigned long long u64;

// ---------------- f32x2 helpers ----------------
__device__ __forceinline__ void ffma2(u64& acc, u64 a, u64 b) {
    asm("fma.rn.f32x2 %0, %1, %2, %0;" : "+l"(acc) : "l"(a), "l"(b));
}
__device__ __forceinline__ u64 dup2(float x) {
    u64 r; asm("mov.b64 %0, {%1, %1};" : "=l"(r) : "f"(x)); return r;
}
__device__ __forceinline__ float2 unpack2(u64 a) {
    float2 f; asm("mov.b64 {%0, %1}, %2;" : "=f"(f.x), "=f"(f.y) : "l"(a)); return f;
}

// ---------------- device scratch ----------------
__device__ float g_pA[32][HH][NN][DD];   // partials of Xs@FC over 32 d-chunks (16 wide)
__device__ float g_f[HH][NN][DD];        // f = relu(Xs@FC)
__device__ float g_pB[32][HH][NN][MM];   // partials of cat@W1 over 32 c-chunks (16 wide)
__device__ float g_out[NN * DD];         // conv accumulation (zero-init, reset each call)
__device__ int   g_ctr = 0;

// ================= Kernel A: partial f = Xs @ FC =================
// grid (dc=32, ec=2, h=8) = 512 blocks x 128 thr. Thread owns e-pair ec*128+tid.
// Warp-uniform LDS rows (broadcast); depth-8 LDG pipeline.
__global__ void __launch_bounds__(128) kA(const float* __restrict__ Xs,
                                          const float* __restrict__ FC) {
    const int dc = blockIdx.x, ec = blockIdx.y, h = blockIdx.z, tid = threadIdx.x;
    const int d0 = dc * 16;

    __shared__ __align__(16) float2 xs2[16][18];   // dup pairs [dd][n], col 17 = pad
    for (int idx = tid; idx < 16 * 18; idx += 128) {
        int dd = idx / 18, n = idx - dd * 18;
        float v = (n < NN) ? Xs[n * DD + d0 + dd] : 0.f;
        xs2[dd][n] = make_float2(v, v);
    }
    __syncthreads();

    u64 acc[NN];
#pragma unroll
    for (int n = 0; n < NN; ++n) acc[n] = 0ull;

    // u64 e-pair index: h*131072 + (d0+dd)*256 + ec*128 + tid
    const u64* fc = reinterpret_cast<const u64*>(FC)
                  + (size_t)h * 131072 + (size_t)d0 * 256 + ec * 128 + tid;
    u64 buf[8];
#pragma unroll
    for (int p = 0; p < 8; ++p) buf[p] = fc[(size_t)p * 256];

#pragma unroll
    for (int dd = 0; dd < 16; ++dd) {
        u64 w = buf[dd & 7];
        if (dd + 8 < 16) buf[dd & 7] = fc[(size_t)(dd + 8) * 256];
        const ulonglong2* row = reinterpret_cast<const ulonglong2*>(&xs2[dd][0]);
#pragma unroll
        for (int j = 0; j < 8; ++j) {
            ulonglong2 q = row[j];
            ffma2(acc[2 * j],     q.x, w);
            ffma2(acc[2 * j + 1], q.y, w);
        }
        ffma2(acc[16], *reinterpret_cast<const u64*>(&xs2[dd][16]), w);
    }
    const int e = 2 * (ec * 128 + tid);
#pragma unroll
    for (int n = 0; n < NN; ++n)
        *reinterpret_cast<u64*>(&g_pA[dc][h][n][e]) = acc[n];
}

// ================= Kernel B: reduce f chunk + relu, partial cat @ W1 =================
// grid (cc=32, h=8) = 256 blocks x 128 thr. Thread owns m-pair = tid.
// cc==31 additionally processes the 3 coordinate rows (c = 512..514).
__global__ void __launch_bounds__(128) kB(const float* __restrict__ ROIs,
                                          const float* __restrict__ W1) {
    const int cc = blockIdx.x, h = blockIdx.y, tid = threadIdx.x;
    const int c0 = cc * 16;

    __shared__ __align__(16) float2 cat2[19][18];   // [cp][n]; rows 16..18 = coords

    for (int idx = tid; idx < NN * 16; idx += 128) {
        int n = idx >> 4, cp = idx & 15;
        float v = 0.f;
#pragma unroll
        for (int s = 0; s < 32; ++s) v += g_pA[s][h][n][c0 + cp];
        v = fmaxf(v, 0.f);
        g_f[h][n][c0 + cp] = v;
        cat2[cp][n] = make_float2(v, v);
    }
    if (tid < 19) cat2[tid][17] = make_float2(0.f, 0.f);   // pad column
    if (cc == 31) {
        for (int idx = tid; idx < NN * 3; idx += 128) {
            int n = idx / 3, j = idx % 3;
            float v = ROIs[idx];
            cat2[16 + j][n] = make_float2(v, v);
        }
    }
    __syncthreads();

    u64 acc[NN];
#pragma unroll
    for (int n = 0; n < NN; ++n) acc[n] = 0ull;

    // u64 index: h*65920 + (c0+i)*128 + tid   (CIN*MM/2 = 65920, MM/2 = 128)
    const u64* w1 = reinterpret_cast<const u64*>(W1)
                  + (size_t)h * 65920 + (size_t)c0 * 128 + tid;
    u64 buf[8];
#pragma unroll
    for (int p = 0; p < 8; ++p) buf[p] = w1[(size_t)p * 128];

#pragma unroll
    for (int i = 0; i < 16; ++i) {
        u64 w = buf[i & 7];
        if (i + 8 < 16) buf[i & 7] = w1[(size_t)(i + 8) * 128];
        const ulonglong2* row = reinterpret_cast<const ulonglong2*>(&cat2[i][0]);
#pragma unroll
        for (int j = 0; j < 8; ++j) {
            ulonglong2 q = row[j];
            ffma2(acc[2 * j],     q.x, w);
            ffma2(acc[2 * j + 1], q.y, w);
        }
        ffma2(acc[16], *reinterpret_cast<const u64*>(&cat2[i][16]), w);
    }
    if (cc == 31) {
#pragma unroll
        for (int j3 = 0; j3 < 3; ++j3) {
            u64 w = reinterpret_cast<const u64*>(W1)[(size_t)h * 65920 + (size_t)(DD + j3) * 128 + tid];
            const ulonglong2* row = reinterpret_cast<const ulonglong2*>(&cat2[16 + j3][0]);
#pragma unroll
            for (int j = 0; j < 8; ++j) {
                ulonglong2 q = row[j];
                ffma2(acc[2 * j],     q.x, w);
                ffma2(acc[2 * j + 1], q.y, w);
            }
            ffma2(acc[16], *reinterpret_cast<const u64*>(&cat2[16 + j3][16]), w);
        }
    }
#pragma unroll
    for (int n = 0; n < NN; ++n)
        *reinterpret_cast<u64*>(&g_pB[cc][h][n][2 * tid]) = acc[n];
}

// ================= Kernel C: tanh + logits + softmax + att@f + epilogue =================
// grid 8 (head) x 512 thr
__global__ void __launch_bounds__(512) kC(const float* __restrict__ W2,
                                          const float* __restrict__ b1,
                                          const float* __restrict__ b2,
                                          const float* __restrict__ conv_w,
                                          const float* __restrict__ conv_b,
                                          const float* __restrict__ Xs,
                                          const float* __restrict__ ROIs,
                                          float* __restrict__ out, int out_size) {
    const int h = blockIdx.x, tid = threadIdx.x;

    __shared__ __align__(16) float hdnf[MM * 20];   // [m*20 + n] (pairs readable as u64)
    __shared__ float patt[16][NN][20];              // per-warp partial logits
    __shared__ float att[NN][NN];                   // logits [k][n]
    __shared__ u64  attw[NN * NN];                  // dup pairs conv_w*softmax [k*17+n]
    __shared__ int  sflag;

    // phase 1: reduce 32 g_pB slices (float4) + bias + tanh -> transposed hdnf
    for (int idx = tid; idx < NN * 64; idx += 512) {
        int n = idx >> 6, m4 = (idx & 63) * 4;
        float4 s = *reinterpret_cast<const float4*>(b1 + h * MM + m4);
#pragma unroll
        for (int cc = 0; cc < 32; ++cc) {
            float4 v = *reinterpret_cast<const float4*>(&g_pB[cc][h][n][m4]);
            s.x += v.x; s.y += v.y; s.z += v.z; s.w += v.w;
        }
        hdnf[(m4 + 0) * 20 + n] = tanhf(s.x);
        hdnf[(m4 + 1) * 20 + n] = tanhf(s.y);
        hdnf[(m4 + 2) * 20 + n] = tanhf(s.z);
        hdnf[(m4 + 3) * 20 + n] = tanhf(s.w);
    }
    if (tid < MM) hdnf[tid * 20 + 17] = 0.f;   // pad lane
    __syncthreads();

    // phase 2: logits = hdn @ W2; warp mq covers 16 m's, lane = k
    {
        const int mq = tid >> 5, lane = tid & 31;
        if (lane < NN) {
            u64 acc2[9];
#pragma unroll
            for (int j = 0; j < 9; ++j) acc2[j] = 0ull;
#pragma unroll
            for (int mm = 0; mm < 16; ++mm) {
                const int m = mq * 16 + mm;
                u64 w2 = dup2(W2[((size_t)h * MM + m) * NN + lane]);
                const ulonglong2* row = reinterpret_cast<const ulonglong2*>(&hdnf[m * 20]);
#pragma unroll
                for (int j = 0; j < 4; ++j) {
                    ulonglong2 q = row[j];
                    ffma2(acc2[2 * j],     q.x, w2);
                    ffma2(acc2[2 * j + 1], q.y, w2);
                }
                ffma2(acc2[8], *reinterpret_cast<const u64*>(&hdnf[m * 20 + 16]), w2);
            }
#pragma unroll
            for (int j = 0; j < 9; ++j) {
                float2 v = unpack2(acc2[j]);
                patt[mq][2 * j][lane] = v.x;
                if (2 * j + 1 < NN) patt[mq][2 * j + 1][lane] = v.y;
            }
        }
    }
    __syncthreads();

    for (int idx = tid; idx < NN * NN; idx += 512) {
        int n = idx / NN, k = idx % NN;
        float s = b2[h * NN + k];
#pragma unroll
        for (int q = 0; q < 16; ++q) s += patt[q][n][k];
        att[k][n] = s;
    }
    __syncthreads();

    // phase 3: softmax over n, premultiply conv_w
    if (tid < NN) {
        const int k = tid;
        float mx = -1e30f;
#pragma unroll
        for (int n = 0; n < NN; ++n) mx = fmaxf(mx, att[k][n]);
        float ex[NN], sum = 0.f;
#pragma unroll
        for (int n = 0; n < NN; ++n) { ex[n] = expf(att[k][n] - mx); sum += ex[n]; }
        float scale = conv_w[h] / sum;
#pragma unroll
        for (int n = 0; n < NN; ++n) attw[k * NN + n] = dup2(ex[n] * scale);
    }
    __syncthreads();

    // phase 4: this head's conv contribution -> atomic accumulate into g_out
    {
        const int ng  = tid >> 8;        // 0: n 0..8, 1: n 9..16
        const int dp  = tid & 255;       // d-pair index
        const int nlo = ng ? 9 : 0, nhi = ng ? 17 : 9;

        u64 acc[NN];
#pragma unroll
        for (int k = 0; k < NN; ++k) acc[k] = 0ull;

        for (int n = nlo; n < nhi; ++n) {
            u64 f2 = *reinterpret_cast<const u64*>(&g_f[h][n][2 * dp]);
#pragma unroll
            for (int k = 0; k < NN; ++k)
                ffma2(acc[k], attw[k * NN + n], f2);
        }
#pragma unroll
        for (int k = 0; k < NN; ++k) {
            float2 v = unpack2(acc[k]);
            atomicAdd(&g_out[k * DD + 2 * dp],     v.x);
            atomicAdd(&g_out[k * DD + 2 * dp + 1], v.y);
        }
    }

    // last-block epilogue
    __threadfence();
    __syncthreads();
    if (tid == 0) sflag = (atomicAdd(&g_ctr, 1) == HH - 1);
    __syncthreads();
    if (sflag) {
        const float cb = conv_b[0];
        volatile float* go = g_out;
        for (int idx = tid; idx < NN * DD; idx += 512) {
            float v = go[idx];
            out[idx] = fmaxf(v + cb, 0.f) + Xs[idx];
            g_out[idx] = 0.f;                       // reset for next replay
        }
        if (tid < NN * 3 && out_size >= NN * DD + NN * 3)
            out[NN * DD + tid] = ROIs[tid];
        if (tid == 0) g_ctr = 0;
    }
}

// ---------------- launch ----------------
extern "C" void kernel_launch(void* const* d_in, const int* in_sizes, int n_in,
                              void* d_out, int out_size) {
    const float *Xs = 0, *ROIs = 0, *FC = 0, *W1 = 0, *b1 = 0, *W2 = 0, *b2 = 0,
                *cw = 0, *cb = 0;
    for (int i = 0; i < n_in; ++i) {
        const float* p = (const float*)d_in[i];
        switch (in_sizes[i]) {
            case NN * DD:       Xs = p; break;
            case NN * 3:        ROIs = p; break;
            case NN * NN:       /* adj */ break;
            case HH * DD * DD:  FC = p; break;
            case HH * CIN * MM: W1 = p; break;
            case HH * MM:       b1 = p; break;
            case HH * MM * NN:  W2 = p; break;
            case HH * NN:       b2 = p; break;
            case HH:            cw = p; break;
            case 1:             cb = p; break;
            default: break;
        }
    }
    float* out = (float*)d_out;

    kA<<<dim3(32, 2, 8), 128>>>(Xs, FC);
    kB<<<dim3(32, 8), 128>>>(ROIs, W1);
    kC<<<HH, 512>>>(W2, b1, b2, cw, cb, Xs, ROIs, out, out_size);
}

// round 8
// speedup vs baseline: 1.0616x; 1.0616x over previous
#include <cuda_runtime.h>
#include <math.h>

#define NN 17
#define DD 512
#define HH 8
#define MM 256
#define CIN 515

typedef unsigned long long u64;

// ---------------- f32x2 helpers ----------------
__device__ __forceinline__ void ffma2(u64& acc, u64 a, u64 b) {
    asm("fma.rn.f32x2 %0, %1, %2, %0;" : "+l"(acc) : "l"(a), "l"(b));
}
__device__ __forceinline__ u64 dup2(float x) {
    u64 r; asm("mov.b64 %0, {%1, %1};" : "=l"(r) : "f"(x)); return r;
}
__device__ __forceinline__ u64 pack2(float x, float y) {
    u64 r; asm("mov.b64 %0, {%1, %2};" : "=l"(r) : "f"(x), "f"(y)); return r;
}
__device__ __forceinline__ float2 unpack2(u64 a) {
    float2 f; asm("mov.b64 {%0, %1}, %2;" : "=f"(f.x), "=f"(f.y) : "l"(a)); return f;
}

// ---------------- device scratch ----------------
__device__ float g_pA[32][HH][NN][DD];   // Xs@FC partials, 32 d-chunks (16 wide)
__device__ float g_f[HH][NN][DD];        // f = relu(Xs@FC)
__device__ float g_pB[64][HH][NN][MM];   // cat@W1 partials, 64 c-chunks (8 wide)
__device__ u64   g_hdnp[HH][MM][9];      // tanh hidden, dup-pair packed [m][(n,n+1)]
__device__ u64   g_attw[HH][NN * NN];    // dup pairs conv_w*softmax, [h][k*17+n]

// ================= Kernel A: partial f = Xs @ FC =================
// grid (dc=32, ec=2, h=8) = 512 blocks x 256 thr.
// Group g = tid>>7: g0 computes n 0..8, g1 computes n 9..16 (same e-pairs).
__global__ void __launch_bounds__(256) kA(const float* __restrict__ Xs,
                                          const float* __restrict__ FC) {
    const int dc = blockIdx.x, ec = blockIdx.y, h = blockIdx.z, tid = threadIdx.x;
    const int d0 = dc * 16;
    const int g = tid >> 7;
    const int P = ec * 128 + (tid & 127);   // e-pair index

    __shared__ __align__(16) u64 xsd[2][16][10];   // dup pairs [grp][dd][slot]
    for (int idx = tid; idx < 16 * 20; idx += 256) {
        int dd = idx / 20, s = idx % 20;
        int gg = s / 10, j = s % 10;
        int n = gg ? 9 + j : j;
        bool ok = gg ? (j < 8) : (j < 9);
        float v = ok ? Xs[n * DD + d0 + dd] : 0.f;
        xsd[gg][dd][j] = dup2(v);
    }
    __syncthreads();

    u64 acc[10];
#pragma unroll
    for (int j = 0; j < 10; ++j) acc[j] = 0ull;

    const u64* fc = reinterpret_cast<const u64*>(FC)
                  + (size_t)h * 131072 + (size_t)d0 * 256 + P;
    u64 buf[8];
#pragma unroll
    for (int p = 0; p < 8; ++p) buf[p] = fc[(size_t)p * 256];

#pragma unroll
    for (int dd = 0; dd < 16; ++dd) {
        u64 w = buf[dd & 7];
        if (dd < 8) buf[dd & 7] = fc[(size_t)(dd + 8) * 256];
        const ulonglong2* row = reinterpret_cast<const ulonglong2*>(&xsd[g][dd][0]);
#pragma unroll
        for (int j = 0; j < 5; ++j) {
            ulonglong2 q = row[j];
            ffma2(acc[2 * j],     q.x, w);
            ffma2(acc[2 * j + 1], q.y, w);
        }
    }
    if (g == 0) {
#pragma unroll
        for (int j = 0; j < 9; ++j)
            *reinterpret_cast<u64*>(&g_pA[dc][h][j][2 * P]) = acc[j];
    } else {
#pragma unroll
        for (int j = 0; j < 8; ++j)
            *reinterpret_cast<u64*>(&g_pA[dc][h][9 + j][2 * P]) = acc[j];
    }
}

// ================= Kernel B: reduce f chunk + relu, partial cat @ W1 =================
// grid (cc=64, h=8) = 512 blocks x 256 thr. Group split over n like kA.
// cc==63 additionally handles the 3 coordinate rows.
__global__ void __launch_bounds__(256) kB(const float* __restrict__ ROIs,
                                          const float* __restrict__ W1) {
    const int cc = blockIdx.x, h = blockIdx.y, tid = threadIdx.x;
    const int c0 = cc * 8;
    const int g = tid >> 7;
    const int mp = tid & 127;   // m-pair

    __shared__ __align__(16) u64 catd[2][11][10];   // rows 0..7 c, 8..10 coords

    // zero (covers pads + coord rows when cc != 63)
    for (int idx = tid; idx < 2 * 11 * 10; idx += 256)
        reinterpret_cast<u64*>(catd)[idx] = 0ull;
    __syncthreads();

    // reduce g_pA slices + relu -> g_f + dup pairs
    if (tid < NN * 8) {
        int n = tid >> 3, cp = tid & 7;
        float v = 0.f;
#pragma unroll
        for (int s = 0; s < 32; ++s) v += g_pA[s][h][n][c0 + cp];
        v = fmaxf(v, 0.f);
        g_f[h][n][c0 + cp] = v;
        if (n < 9) catd[0][cp][n] = dup2(v);
        else       catd[1][cp][n - 9] = dup2(v);
    }
    if (cc == 63 && tid < NN * 3) {
        int n = tid / 3, jj = tid % 3;
        float v = ROIs[tid];
        if (n < 9) catd[0][8 + jj][n] = dup2(v);
        else       catd[1][8 + jj][n - 9] = dup2(v);
    }
    __syncthreads();

    u64 acc[10];
#pragma unroll
    for (int j = 0; j < 10; ++j) acc[j] = 0ull;

    const u64* w1 = reinterpret_cast<const u64*>(W1)
                  + (size_t)h * 65920 + (size_t)c0 * 128 + mp;
    u64 buf[8];
#pragma unroll
    for (int p = 0; p < 8; ++p) buf[p] = w1[(size_t)p * 128];

#pragma unroll
    for (int i = 0; i < 8; ++i) {
        u64 w = buf[i];
        const ulonglong2* row = reinterpret_cast<const ulonglong2*>(&catd[g][i][0]);
#pragma unroll
        for (int j = 0; j < 5; ++j) {
            ulonglong2 q = row[j];
            ffma2(acc[2 * j],     q.x, w);
            ffma2(acc[2 * j + 1], q.y, w);
        }
    }
    if (cc == 63) {
#pragma unroll
        for (int jj = 0; jj < 3; ++jj) {
            u64 w = reinterpret_cast<const u64*>(W1)[(size_t)h * 65920 + (size_t)(DD + jj) * 128 + mp];
            const ulonglong2* row = reinterpret_cast<const ulonglong2*>(&catd[g][8 + jj][0]);
#pragma unroll
            for (int j = 0; j < 5; ++j) {
                ulonglong2 q = row[j];
                ffma2(acc[2 * j],     q.x, w);
                ffma2(acc[2 * j + 1], q.y, w);
            }
        }
    }
    if (g == 0) {
#pragma unroll
        for (int j = 0; j < 9; ++j)
            *reinterpret_cast<u64*>(&g_pB[cc][h][j][2 * mp]) = acc[j];
    } else {
#pragma unroll
        for (int j = 0; j < 8; ++j)
            *reinterpret_cast<u64*>(&g_pB[cc][h][9 + j][2 * mp]) = acc[j];
    }
}

// ================= Kernel C1: reduce g_pB + bias + tanh -> packed g_hdnp =================
// grid (mc=8, h=8) = 64 blocks x 256 thr; block handles 32 m's of head h.
__global__ void __launch_bounds__(256) kC1(const float* __restrict__ b1) {
    const int mc = blockIdx.x, h = blockIdx.y, tid = threadIdx.x;
    const int m0 = mc * 32;

    __shared__ float hdnf[32][20];   // [local m][n], col 17 = pad

    if (tid < NN * 8) {
        int n = tid >> 3, q = tid & 7;
        int m4 = m0 + q * 4;
        float4 s = *reinterpret_cast<const float4*>(b1 + h * MM + m4);
#pragma unroll
        for (int cc = 0; cc < 64; ++cc) {
            float4 v = *reinterpret_cast<const float4*>(&g_pB[cc][h][n][m4]);
            s.x += v.x; s.y += v.y; s.z += v.z; s.w += v.w;
        }
        int lm = q * 4;
        hdnf[lm + 0][n] = tanhf(s.x);
        hdnf[lm + 1][n] = tanhf(s.y);
        hdnf[lm + 2][n] = tanhf(s.z);
        hdnf[lm + 3][n] = tanhf(s.w);
    }
    if (tid < 32) hdnf[tid][17] = 0.f;
    __syncthreads();

    for (int idx = tid; idx < 32 * 9; idx += 256) {
        int lm = idx / 9, j = idx % 9;
        g_hdnp[h][m0 + lm][j] = pack2(hdnf[lm][2 * j], hdnf[lm][2 * j + 1]);
    }
}

// ================= Kernel C2: logits = hdn @ W2, softmax, premult conv_w =================
// grid 8 (head) x 512 thr
__global__ void __launch_bounds__(512) kC2(const float* __restrict__ W2,
                                           const float* __restrict__ b2,
                                           const float* __restrict__ conv_w) {
    const int h = blockIdx.x, tid = threadIdx.x;

    __shared__ __align__(16) u64 hdnp_s[MM][10];   // [m][n-pair j], slot 9 pad
    __shared__ float patt[16][NN][20];
    __shared__ float att[NN][NN];

    for (int idx = tid; idx < MM * 9; idx += 512) {
        int m = idx / 9, j = idx % 9;
        hdnp_s[m][j] = g_hdnp[h][m][j];
    }
    __syncthreads();

    {
        const int mq = tid >> 5, lane = tid & 31;
        if (lane < NN) {
            u64 acc2[9];
#pragma unroll
            for (int j = 0; j < 9; ++j) acc2[j] = 0ull;
#pragma unroll
            for (int mm = 0; mm < 16; ++mm) {
                const int m = mq * 16 + mm;
                u64 w2 = dup2(W2[((size_t)h * MM + m) * NN + lane]);
                const ulonglong2* row = reinterpret_cast<const ulonglong2*>(&hdnp_s[m][0]);
#pragma unroll
                for (int j = 0; j < 4; ++j) {
                    ulonglong2 q = row[j];
                    ffma2(acc2[2 * j],     q.x, w2);
                    ffma2(acc2[2 * j + 1], q.y, w2);
                }
                ffma2(acc2[8], hdnp_s[m][8], w2);
            }
#pragma unroll
            for (int j = 0; j < 9; ++j) {
                float2 v = unpack2(acc2[j]);
                patt[mq][2 * j][lane] = v.x;
                if (2 * j + 1 < NN) patt[mq][2 * j + 1][lane] = v.y;
            }
        }
    }
    __syncthreads();

    for (int idx = tid; idx < NN * NN; idx += 512) {
        int n = idx / NN, k = idx % NN;
        float s = b2[h * NN + k];
#pragma unroll
        for (int q = 0; q < 16; ++q) s += patt[q][n][k];
        att[k][n] = s;
    }
    __syncthreads();

    if (tid < NN) {
        const int k = tid;
        float mx = -1e30f;
#pragma unroll
        for (int n = 0; n < NN; ++n) mx = fmaxf(mx, att[k][n]);
        float ex[NN], sum = 0.f;
#pragma unroll
        for (int n = 0; n < NN; ++n) { ex[n] = expf(att[k][n] - mx); sum += ex[n]; }
        float scale = conv_w[h] / sum;
#pragma unroll
        for (int n = 0; n < NN; ++n) g_attw[h][k * NN + n] = dup2(ex[n] * scale);
    }
}

// ================= Kernel C3: out = relu(sum_{h,n} attw*f + cb) + Xs =================
// grid (k=17, ec=2) = 34 blocks x 256 thr. Group hg = tid>>7 covers 4 heads.
__global__ void __launch_bounds__(256) kC3(const float* __restrict__ Xs,
                                           const float* __restrict__ ROIs,
                                           const float* __restrict__ conv_b,
                                           float* __restrict__ out, int out_size) {
    const int k = blockIdx.x, ec = blockIdx.y, tid = threadIdx.x;
    const int hg = tid >> 7, dt = tid & 127;
    const int P = ec * 128 + dt;   // e-pair

    __shared__ u64 aw[HH][NN];
    __shared__ float2 part[128];

    if (tid < HH * NN)
        aw[tid / NN][tid % NN] = g_attw[tid / NN][k * NN + tid % NN];
    __syncthreads();

    const u64* fb = reinterpret_cast<const u64*>(g_f) + P;
    const int hb = hg * 4;

    u64 acc[4];
#pragma unroll
    for (int j = 0; j < 4; ++j) acc[j] = 0ull;

#pragma unroll
    for (int hh = 0; hh < 4; ++hh) {
        const int h = hb + hh;
#pragma unroll
        for (int n = 0; n < NN; ++n) {
            u64 f2 = fb[(size_t)(h * NN + n) * 256];
            ffma2(acc[(hh * NN + n) & 3], aw[h][n], f2);
        }
    }
    float2 a0 = unpack2(acc[0]), a1 = unpack2(acc[1]);
    float2 a2 = unpack2(acc[2]), a3 = unpack2(acc[3]);
    float2 s = make_float2(a0.x + a1.x + a2.x + a3.x,
                           a0.y + a1.y + a2.y + a3.y);
    if (hg == 1) part[dt] = s;
    __syncthreads();
    if (hg == 0) {
        const float cb = conv_b[0];
        float rx = s.x + part[dt].x + cb;
        float ry = s.y + part[dt].y + cb;
        const float2 xv = *reinterpret_cast<const float2*>(Xs + k * DD + 2 * P);
        float2 r = make_float2(fmaxf(rx, 0.f) + xv.x, fmaxf(ry, 0.f) + xv.y);
        *reinterpret_cast<float2*>(out + k * DD + 2 * P) = r;
    }

    if (k == 0 && ec == 0 && tid < NN * 3 && out_size >= NN * DD + NN * 3)
        out[NN * DD + tid] = ROIs[tid];
}

// ---------------- launch ----------------
extern "C" void kernel_launch(void* const* d_in, const int* in_sizes, int n_in,
                              void* d_out, int out_size) {
    const float *Xs = 0, *ROIs = 0, *FC = 0, *W1 = 0, *b1 = 0, *W2 = 0, *b2 = 0,
                *cw = 0, *cb = 0;
    for (int i = 0; i < n_in; ++i) {
        const float* p = (const float*)d_in[i];
        switch (in_sizes[i]) {
            case NN * DD:       Xs = p; break;
            case NN * 3:        ROIs = p; break;
            case NN * NN:       /* adj */ break;
            case HH * DD * DD:  FC = p; break;
            case HH * CIN * MM: W1 = p; break;
            case HH * MM:       b1 = p; break;
            case HH * MM * NN:  W2 = p; break;
            case HH * NN:       b2 = p; break;
            case HH:            cw = p; break;
            case 1:             cb = p; break;
            default: break;
        }
    }
    float* out = (float*)d_out;

    kA<<<dim3(32, 2, 8), 256>>>(Xs, FC);
    kB<<<dim3(64, 8), 256>>>(ROIs, W1);
    kC1<<<dim3(8, 8), 256>>>(b1);
    kC2<<<HH, 512>>>(W2, b2, cw);
    kC3<<<dim3(NN, 2), 256>>>(Xs, ROIs, cb, out, out_size);
}